// round 17
// baseline (speedup 1.0000x reference)
#include <cuda_runtime.h>

// out[r, c] = x[r, c] * weight[c]   for x: [32768, 1024] fp32, weight: [1024] fp32
//
// FINAL — machine-roofline kernel (champion, 8x replicated).
// Best measured: 43.49us timed, 35.55us in-window = ~7.55 TB/s
// (~94% of 8 TB/s HBM spec) for the irreducible 268 MB stream.
//
// 16-round evidence base:
// - Steady-state BW invariant (7.2-7.5 TB/s) across occupancy 32-77%,
//   MLP 4-8, CTA 128/256/512, 128b vs 256b accesses, .cs vs .wt stores.
// - One-shot fine-grained CTAs win; persistent kernels lose (chunk-boundary
//   drains -8%; local-memory-demoted double-buffer -19%); fat CTAs lose
//   (register bloat, occupancy quantization).
// - Timed = in-window + ~7.8us fixed graph-replay overhead (harness-side).
// - Noise on identical SASS: timed 43.49-44.7us, window 35.5-36.8us.

static constexpr int ROWS = 32768;
static constexpr int COLS = 1024;
static constexpr unsigned N_VEC4 = (unsigned)ROWS * (COLS / 4);   // 8,388,608
static constexpr int THREADS = 256;
static constexpr int VEC_PER_THREAD = 8;
static constexpr int BLOCKS = (int)(N_VEC4 / (THREADS * VEC_PER_THREAD)); // 4096
static constexpr int COLS_VEC4 = COLS / 4;                        // 256
static_assert(THREADS == COLS_VEC4, "weight-hoist relies on THREADS == COLS/4");
static_assert((unsigned)BLOCKS * THREADS * VEC_PER_THREAD == N_VEC4, "exact cover");

__global__ __launch_bounds__(THREADS)
void diag_weight_kernel(const float4* __restrict__ x,
                        const float4* __restrict__ w,
                        float4* __restrict__ out) {
    const unsigned tid = threadIdx.x;
    // Block covers a contiguous span of THREADS*VEC_PER_THREAD float4s;
    // iteration i is offset by i*THREADS (fully coalesced).
    const unsigned base = blockIdx.x * (unsigned)(THREADS * VEC_PER_THREAD) + tid;

    // One weight vector per thread: every index this thread touches is
    // congruent to tid (mod 256). 4 KiB table -> L1-resident after warmup.
    const float4 vw = w[tid];

    float4 vx[VEC_PER_THREAD];

    // Front-batch all 8 streaming loads (MLP burst = 8 per thread; x is
    // single-touch, 256 MB >> 126 MB L2, so evict-first).
#pragma unroll
    for (int i = 0; i < VEC_PER_THREAD; i++) {
        vx[i] = __ldcs(&x[base + (unsigned)i * THREADS]);
    }

#pragma unroll
    for (int i = 0; i < VEC_PER_THREAD; i++) {
        float4 r;
        r.x = vx[i].x * vw.x;
        r.y = vx[i].y * vw.y;
        r.z = vx[i].z * vw.z;
        r.w = vx[i].w * vw.w;
        __stcs(&out[base + (unsigned)i * THREADS], r);
    }
}

extern "C" void kernel_launch(void* const* d_in, const int* in_sizes, int n_in,
                              void* d_out, int out_size) {
    const float4* x = (const float4*)d_in[0];   // [32768, 1024] fp32
    const float4* w = (const float4*)d_in[1];   // [1024] fp32
    float4* out = (float4*)d_out;

    diag_weight_kernel<<<BLOCKS, THREADS>>>(x, w, out);
}